// round 13
// baseline (speedup 1.0000x reference)
#include <cuda_runtime.h>
#include <cuda_bf16.h>

// Wrapped SAT box query, separable inclusion-exclusion form:
//   result[n,c] = sum_{a in Rset} sum_{b in Cset} sgn_a*sgn_b * sat[ia, ib, c]
// Each axis contributes up to 3 (index, sign) terms; dead terms get sign 0 and
// index 0. Index math i(u)=floor(u*512-0.5) is exact and matches JAX bitwise.
//
// R12: 8 channels per thread (2x float4). 18 independent LDG.128 per thread
// = 288 B outstanding -> 2x the MLP of R11. 36 lanes/point, 8 points/block.

#define HDIM 512
#define WDIM 512

__device__ __forceinline__ int sat_index(float u) {
    // floor(u * 512 - 0.5), exact
    return (int)floorf(__fsub_rn(__fmul_rn(u, 512.0f), 0.5f));
}

__device__ __forceinline__ float4 acc9(const float4* v, const float* w) {
    // 3 independent chains per component, then combine (same order as R11)
    float ax = __fmul_rn(w[0], v[0].x), bx = __fmul_rn(w[1], v[1].x), dx = __fmul_rn(w[2], v[2].x);
    float ay = __fmul_rn(w[0], v[0].y), by = __fmul_rn(w[1], v[1].y), dy = __fmul_rn(w[2], v[2].y);
    float az = __fmul_rn(w[0], v[0].z), bz = __fmul_rn(w[1], v[1].z), dz = __fmul_rn(w[2], v[2].z);
    float aw = __fmul_rn(w[0], v[0].w), bw = __fmul_rn(w[1], v[1].w), dw = __fmul_rn(w[2], v[2].w);

    ax = fmaf(w[3], v[3].x, ax); bx = fmaf(w[4], v[4].x, bx); dx = fmaf(w[5], v[5].x, dx);
    ay = fmaf(w[3], v[3].y, ay); by = fmaf(w[4], v[4].y, by); dy = fmaf(w[5], v[5].y, dy);
    az = fmaf(w[3], v[3].z, az); bz = fmaf(w[4], v[4].z, bz); dz = fmaf(w[5], v[5].z, dz);
    aw = fmaf(w[3], v[3].w, aw); bw = fmaf(w[4], v[4].w, bw); dw = fmaf(w[5], v[5].w, dw);

    ax = fmaf(w[6], v[6].x, ax); bx = fmaf(w[7], v[7].x, bx); dx = fmaf(w[8], v[8].x, dx);
    ay = fmaf(w[6], v[6].y, ay); by = fmaf(w[7], v[7].y, by); dy = fmaf(w[8], v[8].y, dy);
    az = fmaf(w[6], v[6].z, az); bz = fmaf(w[7], v[7].z, bz); dz = fmaf(w[8], v[8].z, dz);
    aw = fmaf(w[6], v[6].w, aw); bw = fmaf(w[7], v[7].w, bw); dw = fmaf(w[8], v[8].w, dw);

    float4 r;
    r.x = __fadd_rn(__fadd_rn(ax, bx), dx);
    r.y = __fadd_rn(__fadd_rn(ay, by), dy);
    r.z = __fadd_rn(__fadd_rn(az, bz), dz);
    r.w = __fadd_rn(__fadd_rn(aw, bw), dw);
    return r;
}

__global__ void __launch_bounds__(288, 7) sat_query_v8_kernel(
    const float* __restrict__ sat,
    const float* __restrict__ x,
    const int*   __restrict__ p_start,
    float*       __restrict__ out,
    int C, int C_out, int N)
{
    const int n = blockIdx.x * blockDim.y + threadIdx.y;
    if (n >= N) return;

    int s0 = *p_start;              // uniform, L1-hot; hoisted to overlap setup
    if (s0 < 0) s0 = 0;

    // ---- per-point scalar setup (redundant across 36 lanes; cheap) ----
    const float4 q = __ldg(reinterpret_cast<const float4*>(x) + n);
    float cu = q.x, cv = q.y, du = q.z, dv = q.w;

    float hu = __fmul_rn(du, 0.5f);
    float hv = __fmul_rn(dv, 0.5f);
    float su = __fsub_rn(cu, hu), eu = __fadd_rn(cu, hu);
    float sv = __fsub_rn(cv, hv), ev = __fadd_rn(cv, hv);

    if (du < 0.0f) { float t = su; su = eu; eu = t; }
    if (dv < 0.0f) { float t = sv; sv = ev; ev = t; }

    su = __fsub_rn(su, floorf(su)); eu = __fsub_rn(eu, floorf(eu));
    sv = __fsub_rn(sv, floorf(sv)); ev = __fsub_rn(ev, floorf(ev));

    // ---- per-axis inclusion-exclusion lists (3 slots, dead slot => sign 0) ----
    int   iu_e = sat_index(eu);
    int   iu_s = sat_index(su) - 1;
    bool  wu   = (su > eu);
    int   rI0 = (iu_e >= 0) ? iu_e : 0;  float rS0 = (iu_e >= 0) ? 1.0f : 0.0f;
    int   rI1 = wu ? (HDIM - 1) : 0;     float rS1 = wu ? 1.0f : 0.0f;
    int   rI2 = (iu_s >= 0) ? iu_s : 0;  float rS2 = (iu_s >= 0) ? -1.0f : 0.0f;

    int   iv_e = sat_index(ev);
    int   iv_s = sat_index(sv) - 1;
    bool  wv   = (sv > ev);
    int   cI0 = (iv_e >= 0) ? iv_e : 0;  float cS0 = (iv_e >= 0) ? 1.0f : 0.0f;
    int   cI1 = wv ? (WDIM - 1) : 0;     float cS1 = wv ? 1.0f : 0.0f;
    int   cI2 = (iv_s >= 0) ? iv_s : 0;  float cS2 = (iv_s >= 0) ? -1.0f : 0.0f;

    const int WC = WDIM * C;
    int r0 = rI0 * WC, r1 = rI1 * WC, r2 = rI2 * WC;
    int c0 = cI0 * C,  c1 = cI1 * C,  c2 = cI2 * C;

    int   o[9];
    float w[9];
    o[0] = r0 + c0; o[1] = r0 + c1; o[2] = r0 + c2;
    o[3] = r1 + c0; o[4] = r1 + c1; o[5] = r1 + c2;
    o[6] = r2 + c0; o[7] = r2 + c1; o[8] = r2 + c2;
    w[0] = rS0 * cS0; w[1] = rS0 * cS1; w[2] = rS0 * cS2;
    w[3] = rS1 * cS0; w[4] = rS1 * cS1; w[5] = rS1 * cS2;
    w[6] = rS2 * cS0; w[7] = rS2 * cS1; w[8] = rS2 * cS2;

    const float* __restrict__ satc = sat + s0;
    const size_t obase = (size_t)n * (size_t)C_out;

    const int ch = threadIdx.x * 8;
    if (ch >= C_out) return;

    const bool aligned = ((C & 3) == 0) && ((s0 & 3) == 0) && (ch + 8 <= C_out);

    if (aligned) {
        // ---- fast path: 18 independent LDG.128 issued before any FMA ----
        const float4* __restrict__ p = reinterpret_cast<const float4*>(satc + ch);
        float4 va[9], vb[9];
        #pragma unroll
        for (int s = 0; s < 9; s++) {
            int q4 = o[s] >> 2;          // offsets are multiples of 4 floats
            va[s] = __ldg(p + q4);
            vb[s] = __ldg(p + q4 + 1);
        }
        float4 ra = acc9(va, w);
        float4 rb = acc9(vb, w);
        *reinterpret_cast<float4*>(out + obase + ch)     = ra;
        *reinterpret_cast<float4*>(out + obase + ch + 4) = rb;
    } else {
        // ---- generic scalar path (sliced / unaligned / tail channels) ----
        #pragma unroll
        for (int k = 0; k < 8; k++) {
            int c = ch + k;
            if (c >= C_out) break;
            float acc;
            acc = __fmul_rn(w[0], satc[o[0] + c]);
            acc = fmaf(w[1], satc[o[1] + c], acc);
            acc = fmaf(w[2], satc[o[2] + c], acc);
            acc = fmaf(w[3], satc[o[3] + c], acc);
            acc = fmaf(w[4], satc[o[4] + c], acc);
            acc = fmaf(w[5], satc[o[5] + c], acc);
            acc = fmaf(w[6], satc[o[6] + c], acc);
            acc = fmaf(w[7], satc[o[7] + c], acc);
            acc = fmaf(w[8], satc[o[8] + c], acc);
            out[obase + c] = acc;
        }
    }
}

extern "C" void kernel_launch(void* const* d_in, const int* in_sizes, int n_in,
                              void* d_out, int out_size) {
    const float* sat   = (const float*)d_in[0];
    const float* x     = (const float*)d_in[1];
    const int*   start = (const int*)d_in[2];

    const int N     = in_sizes[1] / 4;
    const int C     = in_sizes[0] / (HDIM * WDIM);
    const int C_out = out_size / N;

    int lanes = (C_out + 7) / 8;          // 8-channel lanes per point (36 for C=288)
    if (lanes < 1) lanes = 1;
    if (lanes > 1024) lanes = 1024;

    int ppb = 1024 / lanes;               // points per block
    if (ppb > 8) ppb = 8;
    if (ppb < 1) ppb = 1;

    dim3 bd(lanes, ppb);
    int grid = (N + ppb - 1) / ppb;

    sat_query_v8_kernel<<<grid, bd>>>(sat, x, start, (float*)d_out, C, C_out, N);
}

// round 14
// speedup vs baseline: 1.3716x; 1.3716x over previous
#include <cuda_runtime.h>
#include <cuda_bf16.h>

// Wrapped SAT box query, separable inclusion-exclusion form:
//   result[n,c] = sum_{a in Rset} sum_{b in Cset} sgn_a*sgn_b * sat[ia, ib, c]
// Each axis contributes up to 3 (index, sign) terms; dead terms get sign 0 and
// index 0. Index math i(u)=floor(u*512-0.5) is exact and matches JAX bitwise.
//
// R13: the R12 8-channel/thread kernel, but with a sane register budget.
// R12's __launch_bounds__(288,7) forced 32 regs -> the 18-float4 load batch
// spilled and serialized (L1 75%, issue 18%). (288,2) gives ~113 regs: the
// full 18 independent LDG.128 (288 B/thread in flight) actually materializes.
// 576 threads/SM x 288 B = 166 KB in flight/SM >> ~26 KB needed to cover
// DRAM latency at the LTS cap, so 28% occupancy is sufficient by design.

#define HDIM 512
#define WDIM 512

__device__ __forceinline__ int sat_index(float u) {
    // floor(u * 512 - 0.5), exact
    return (int)floorf(__fsub_rn(__fmul_rn(u, 512.0f), 0.5f));
}

__device__ __forceinline__ float4 acc9(const float4* v, const float* w) {
    // 3 independent chains per component, then combine
    float ax = __fmul_rn(w[0], v[0].x), bx = __fmul_rn(w[1], v[1].x), dx = __fmul_rn(w[2], v[2].x);
    float ay = __fmul_rn(w[0], v[0].y), by = __fmul_rn(w[1], v[1].y), dy = __fmul_rn(w[2], v[2].y);
    float az = __fmul_rn(w[0], v[0].z), bz = __fmul_rn(w[1], v[1].z), dz = __fmul_rn(w[2], v[2].z);
    float aw = __fmul_rn(w[0], v[0].w), bw = __fmul_rn(w[1], v[1].w), dw = __fmul_rn(w[2], v[2].w);

    ax = fmaf(w[3], v[3].x, ax); bx = fmaf(w[4], v[4].x, bx); dx = fmaf(w[5], v[5].x, dx);
    ay = fmaf(w[3], v[3].y, ay); by = fmaf(w[4], v[4].y, by); dy = fmaf(w[5], v[5].y, dy);
    az = fmaf(w[3], v[3].z, az); bz = fmaf(w[4], v[4].z, bz); dz = fmaf(w[5], v[5].z, dz);
    aw = fmaf(w[3], v[3].w, aw); bw = fmaf(w[4], v[4].w, bw); dw = fmaf(w[5], v[5].w, dw);

    ax = fmaf(w[6], v[6].x, ax); bx = fmaf(w[7], v[7].x, bx); dx = fmaf(w[8], v[8].x, dx);
    ay = fmaf(w[6], v[6].y, ay); by = fmaf(w[7], v[7].y, by); dy = fmaf(w[8], v[8].y, dy);
    az = fmaf(w[6], v[6].z, az); bz = fmaf(w[7], v[7].z, bz); dz = fmaf(w[8], v[8].z, dz);
    aw = fmaf(w[6], v[6].w, aw); bw = fmaf(w[7], v[7].w, bw); dw = fmaf(w[8], v[8].w, dw);

    float4 r;
    r.x = __fadd_rn(__fadd_rn(ax, bx), dx);
    r.y = __fadd_rn(__fadd_rn(ay, by), dy);
    r.z = __fadd_rn(__fadd_rn(az, bz), dz);
    r.w = __fadd_rn(__fadd_rn(aw, bw), dw);
    return r;
}

__global__ void __launch_bounds__(288, 2) sat_query_v8_kernel(
    const float* __restrict__ sat,
    const float* __restrict__ x,
    const int*   __restrict__ p_start,
    float*       __restrict__ out,
    int C, int C_out, int N)
{
    const int n = blockIdx.x * blockDim.y + threadIdx.y;
    if (n >= N) return;

    int s0 = *p_start;              // uniform, L1-hot; hoisted to overlap setup
    if (s0 < 0) s0 = 0;

    // ---- per-point scalar setup (redundant across 36 lanes; cheap) ----
    const float4 q = __ldg(reinterpret_cast<const float4*>(x) + n);
    float cu = q.x, cv = q.y, du = q.z, dv = q.w;

    float hu = __fmul_rn(du, 0.5f);
    float hv = __fmul_rn(dv, 0.5f);
    float su = __fsub_rn(cu, hu), eu = __fadd_rn(cu, hu);
    float sv = __fsub_rn(cv, hv), ev = __fadd_rn(cv, hv);

    if (du < 0.0f) { float t = su; su = eu; eu = t; }
    if (dv < 0.0f) { float t = sv; sv = ev; ev = t; }

    su = __fsub_rn(su, floorf(su)); eu = __fsub_rn(eu, floorf(eu));
    sv = __fsub_rn(sv, floorf(sv)); ev = __fsub_rn(ev, floorf(ev));

    // ---- per-axis inclusion-exclusion lists (3 slots, dead slot => sign 0) ----
    int   iu_e = sat_index(eu);
    int   iu_s = sat_index(su) - 1;
    bool  wu   = (su > eu);
    int   rI0 = (iu_e >= 0) ? iu_e : 0;  float rS0 = (iu_e >= 0) ? 1.0f : 0.0f;
    int   rI1 = wu ? (HDIM - 1) : 0;     float rS1 = wu ? 1.0f : 0.0f;
    int   rI2 = (iu_s >= 0) ? iu_s : 0;  float rS2 = (iu_s >= 0) ? -1.0f : 0.0f;

    int   iv_e = sat_index(ev);
    int   iv_s = sat_index(sv) - 1;
    bool  wv   = (sv > ev);
    int   cI0 = (iv_e >= 0) ? iv_e : 0;  float cS0 = (iv_e >= 0) ? 1.0f : 0.0f;
    int   cI1 = wv ? (WDIM - 1) : 0;     float cS1 = wv ? 1.0f : 0.0f;
    int   cI2 = (iv_s >= 0) ? iv_s : 0;  float cS2 = (iv_s >= 0) ? -1.0f : 0.0f;

    const int WC = WDIM * C;
    int r0 = rI0 * WC, r1 = rI1 * WC, r2 = rI2 * WC;
    int c0 = cI0 * C,  c1 = cI1 * C,  c2 = cI2 * C;

    int   o[9];
    float w[9];
    o[0] = r0 + c0; o[1] = r0 + c1; o[2] = r0 + c2;
    o[3] = r1 + c0; o[4] = r1 + c1; o[5] = r1 + c2;
    o[6] = r2 + c0; o[7] = r2 + c1; o[8] = r2 + c2;
    w[0] = rS0 * cS0; w[1] = rS0 * cS1; w[2] = rS0 * cS2;
    w[3] = rS1 * cS0; w[4] = rS1 * cS1; w[5] = rS1 * cS2;
    w[6] = rS2 * cS0; w[7] = rS2 * cS1; w[8] = rS2 * cS2;

    const float* __restrict__ satc = sat + s0;
    const size_t obase = (size_t)n * (size_t)C_out;

    const int ch = threadIdx.x * 8;
    if (ch >= C_out) return;

    const bool aligned = ((C & 3) == 0) && ((s0 & 3) == 0) && (ch + 8 <= C_out);

    if (aligned) {
        // ---- fast path: 18 independent LDG.128 issued before any FMA ----
        const float4* __restrict__ p = reinterpret_cast<const float4*>(satc + ch);
        float4 va[9], vb[9];
        #pragma unroll
        for (int s = 0; s < 9; s++) {
            int q4 = o[s] >> 2;          // offsets are multiples of 4 floats
            va[s] = __ldg(p + q4);
            vb[s] = __ldg(p + q4 + 1);
        }
        float4 ra = acc9(va, w);
        float4 rb = acc9(vb, w);
        *reinterpret_cast<float4*>(out + obase + ch)     = ra;
        *reinterpret_cast<float4*>(out + obase + ch + 4) = rb;
    } else {
        // ---- generic scalar path (sliced / unaligned / tail channels) ----
        #pragma unroll
        for (int k = 0; k < 8; k++) {
            int c = ch + k;
            if (c >= C_out) break;
            float acc;
            acc = __fmul_rn(w[0], satc[o[0] + c]);
            acc = fmaf(w[1], satc[o[1] + c], acc);
            acc = fmaf(w[2], satc[o[2] + c], acc);
            acc = fmaf(w[3], satc[o[3] + c], acc);
            acc = fmaf(w[4], satc[o[4] + c], acc);
            acc = fmaf(w[5], satc[o[5] + c], acc);
            acc = fmaf(w[6], satc[o[6] + c], acc);
            acc = fmaf(w[7], satc[o[7] + c], acc);
            acc = fmaf(w[8], satc[o[8] + c], acc);
            out[obase + c] = acc;
        }
    }
}

extern "C" void kernel_launch(void* const* d_in, const int* in_sizes, int n_in,
                              void* d_out, int out_size) {
    const float* sat   = (const float*)d_in[0];
    const float* x     = (const float*)d_in[1];
    const int*   start = (const int*)d_in[2];

    const int N     = in_sizes[1] / 4;
    const int C     = in_sizes[0] / (HDIM * WDIM);
    const int C_out = out_size / N;

    int lanes = (C_out + 7) / 8;          // 8-channel lanes per point (36 for C=288)
    if (lanes < 1) lanes = 1;
    if (lanes > 1024) lanes = 1024;

    int ppb = 1024 / lanes;               // points per block
    if (ppb > 8) ppb = 8;
    if (ppb < 1) ppb = 1;

    dim3 bd(lanes, ppb);
    int grid = (N + ppb - 1) / ppb;

    sat_query_v8_kernel<<<grid, bd>>>(sat, x, start, (float*)d_out, C, C_out, N);
}

// round 15
// speedup vs baseline: 1.3734x; 1.0013x over previous
#include <cuda_runtime.h>
#include <cuda_bf16.h>

// Wrapped SAT box query, separable inclusion-exclusion form:
//   result[n,c] = sum_{a in Rset} sum_{b in Cset} sgn_a*sgn_b * sat[ia, ib, c]
// Each axis contributes up to 3 (index, sign) terms; dead terms get sign 0 and
// index 0. Index math i(u)=floor(u*512-0.5) is exact and matches JAX bitwise.
//
// R13: the R12 8-channel/thread kernel, but with a sane register budget.
// R12's __launch_bounds__(288,7) forced 32 regs -> the 18-float4 load batch
// spilled and serialized (L1 75%, issue 18%). (288,2) gives ~113 regs: the
// full 18 independent LDG.128 (288 B/thread in flight) actually materializes.
// 576 threads/SM x 288 B = 166 KB in flight/SM >> ~26 KB needed to cover
// DRAM latency at the LTS cap, so 28% occupancy is sufficient by design.

#define HDIM 512
#define WDIM 512

__device__ __forceinline__ int sat_index(float u) {
    // floor(u * 512 - 0.5), exact
    return (int)floorf(__fsub_rn(__fmul_rn(u, 512.0f), 0.5f));
}

__device__ __forceinline__ float4 acc9(const float4* v, const float* w) {
    // 3 independent chains per component, then combine
    float ax = __fmul_rn(w[0], v[0].x), bx = __fmul_rn(w[1], v[1].x), dx = __fmul_rn(w[2], v[2].x);
    float ay = __fmul_rn(w[0], v[0].y), by = __fmul_rn(w[1], v[1].y), dy = __fmul_rn(w[2], v[2].y);
    float az = __fmul_rn(w[0], v[0].z), bz = __fmul_rn(w[1], v[1].z), dz = __fmul_rn(w[2], v[2].z);
    float aw = __fmul_rn(w[0], v[0].w), bw = __fmul_rn(w[1], v[1].w), dw = __fmul_rn(w[2], v[2].w);

    ax = fmaf(w[3], v[3].x, ax); bx = fmaf(w[4], v[4].x, bx); dx = fmaf(w[5], v[5].x, dx);
    ay = fmaf(w[3], v[3].y, ay); by = fmaf(w[4], v[4].y, by); dy = fmaf(w[5], v[5].y, dy);
    az = fmaf(w[3], v[3].z, az); bz = fmaf(w[4], v[4].z, bz); dz = fmaf(w[5], v[5].z, dz);
    aw = fmaf(w[3], v[3].w, aw); bw = fmaf(w[4], v[4].w, bw); dw = fmaf(w[5], v[5].w, dw);

    ax = fmaf(w[6], v[6].x, ax); bx = fmaf(w[7], v[7].x, bx); dx = fmaf(w[8], v[8].x, dx);
    ay = fmaf(w[6], v[6].y, ay); by = fmaf(w[7], v[7].y, by); dy = fmaf(w[8], v[8].y, dy);
    az = fmaf(w[6], v[6].z, az); bz = fmaf(w[7], v[7].z, bz); dz = fmaf(w[8], v[8].z, dz);
    aw = fmaf(w[6], v[6].w, aw); bw = fmaf(w[7], v[7].w, bw); dw = fmaf(w[8], v[8].w, dw);

    float4 r;
    r.x = __fadd_rn(__fadd_rn(ax, bx), dx);
    r.y = __fadd_rn(__fadd_rn(ay, by), dy);
    r.z = __fadd_rn(__fadd_rn(az, bz), dz);
    r.w = __fadd_rn(__fadd_rn(aw, bw), dw);
    return r;
}

__global__ void __launch_bounds__(288, 2) sat_query_v8_kernel(
    const float* __restrict__ sat,
    const float* __restrict__ x,
    const int*   __restrict__ p_start,
    float*       __restrict__ out,
    int C, int C_out, int N)
{
    const int n = blockIdx.x * blockDim.y + threadIdx.y;
    if (n >= N) return;

    int s0 = *p_start;              // uniform, L1-hot; hoisted to overlap setup
    if (s0 < 0) s0 = 0;

    // ---- per-point scalar setup (redundant across 36 lanes; cheap) ----
    const float4 q = __ldg(reinterpret_cast<const float4*>(x) + n);
    float cu = q.x, cv = q.y, du = q.z, dv = q.w;

    float hu = __fmul_rn(du, 0.5f);
    float hv = __fmul_rn(dv, 0.5f);
    float su = __fsub_rn(cu, hu), eu = __fadd_rn(cu, hu);
    float sv = __fsub_rn(cv, hv), ev = __fadd_rn(cv, hv);

    if (du < 0.0f) { float t = su; su = eu; eu = t; }
    if (dv < 0.0f) { float t = sv; sv = ev; ev = t; }

    su = __fsub_rn(su, floorf(su)); eu = __fsub_rn(eu, floorf(eu));
    sv = __fsub_rn(sv, floorf(sv)); ev = __fsub_rn(ev, floorf(ev));

    // ---- per-axis inclusion-exclusion lists (3 slots, dead slot => sign 0) ----
    int   iu_e = sat_index(eu);
    int   iu_s = sat_index(su) - 1;
    bool  wu   = (su > eu);
    int   rI0 = (iu_e >= 0) ? iu_e : 0;  float rS0 = (iu_e >= 0) ? 1.0f : 0.0f;
    int   rI1 = wu ? (HDIM - 1) : 0;     float rS1 = wu ? 1.0f : 0.0f;
    int   rI2 = (iu_s >= 0) ? iu_s : 0;  float rS2 = (iu_s >= 0) ? -1.0f : 0.0f;

    int   iv_e = sat_index(ev);
    int   iv_s = sat_index(sv) - 1;
    bool  wv   = (sv > ev);
    int   cI0 = (iv_e >= 0) ? iv_e : 0;  float cS0 = (iv_e >= 0) ? 1.0f : 0.0f;
    int   cI1 = wv ? (WDIM - 1) : 0;     float cS1 = wv ? 1.0f : 0.0f;
    int   cI2 = (iv_s >= 0) ? iv_s : 0;  float cS2 = (iv_s >= 0) ? -1.0f : 0.0f;

    const int WC = WDIM * C;
    int r0 = rI0 * WC, r1 = rI1 * WC, r2 = rI2 * WC;
    int c0 = cI0 * C,  c1 = cI1 * C,  c2 = cI2 * C;

    int   o[9];
    float w[9];
    o[0] = r0 + c0; o[1] = r0 + c1; o[2] = r0 + c2;
    o[3] = r1 + c0; o[4] = r1 + c1; o[5] = r1 + c2;
    o[6] = r2 + c0; o[7] = r2 + c1; o[8] = r2 + c2;
    w[0] = rS0 * cS0; w[1] = rS0 * cS1; w[2] = rS0 * cS2;
    w[3] = rS1 * cS0; w[4] = rS1 * cS1; w[5] = rS1 * cS2;
    w[6] = rS2 * cS0; w[7] = rS2 * cS1; w[8] = rS2 * cS2;

    const float* __restrict__ satc = sat + s0;
    const size_t obase = (size_t)n * (size_t)C_out;

    const int ch = threadIdx.x * 8;
    if (ch >= C_out) return;

    const bool aligned = ((C & 3) == 0) && ((s0 & 3) == 0) && (ch + 8 <= C_out);

    if (aligned) {
        // ---- fast path: 18 independent LDG.128 issued before any FMA ----
        const float4* __restrict__ p = reinterpret_cast<const float4*>(satc + ch);
        float4 va[9], vb[9];
        #pragma unroll
        for (int s = 0; s < 9; s++) {
            int q4 = o[s] >> 2;          // offsets are multiples of 4 floats
            va[s] = __ldg(p + q4);
            vb[s] = __ldg(p + q4 + 1);
        }
        float4 ra = acc9(va, w);
        float4 rb = acc9(vb, w);
        *reinterpret_cast<float4*>(out + obase + ch)     = ra;
        *reinterpret_cast<float4*>(out + obase + ch + 4) = rb;
    } else {
        // ---- generic scalar path (sliced / unaligned / tail channels) ----
        #pragma unroll
        for (int k = 0; k < 8; k++) {
            int c = ch + k;
            if (c >= C_out) break;
            float acc;
            acc = __fmul_rn(w[0], satc[o[0] + c]);
            acc = fmaf(w[1], satc[o[1] + c], acc);
            acc = fmaf(w[2], satc[o[2] + c], acc);
            acc = fmaf(w[3], satc[o[3] + c], acc);
            acc = fmaf(w[4], satc[o[4] + c], acc);
            acc = fmaf(w[5], satc[o[5] + c], acc);
            acc = fmaf(w[6], satc[o[6] + c], acc);
            acc = fmaf(w[7], satc[o[7] + c], acc);
            acc = fmaf(w[8], satc[o[8] + c], acc);
            out[obase + c] = acc;
        }
    }
}

extern "C" void kernel_launch(void* const* d_in, const int* in_sizes, int n_in,
                              void* d_out, int out_size) {
    const float* sat   = (const float*)d_in[0];
    const float* x     = (const float*)d_in[1];
    const int*   start = (const int*)d_in[2];

    const int N     = in_sizes[1] / 4;
    const int C     = in_sizes[0] / (HDIM * WDIM);
    const int C_out = out_size / N;

    int lanes = (C_out + 7) / 8;          // 8-channel lanes per point (36 for C=288)
    if (lanes < 1) lanes = 1;
    if (lanes > 1024) lanes = 1024;

    int ppb = 1024 / lanes;               // points per block
    if (ppb > 8) ppb = 8;
    if (ppb < 1) ppb = 1;

    dim3 bd(lanes, ppb);
    int grid = (N + ppb - 1) / ppb;

    sat_query_v8_kernel<<<grid, bd>>>(sat, x, start, (float*)d_out, C, C_out, N);
}